// round 4
// baseline (speedup 1.0000x reference)
#include <cuda_runtime.h>
#include <math.h>

// ---------------- problem constants ----------------
#define BATCHN 8
#define TLEN   1024
#define DM     512          // D_MODEL
#define HH     1024         // H per direction
#define K3H    3072         // 3*H
#define NWALL  6144         // 2*3H  (both directions)
#define NTOK   8192         // B*T
#define GOUT   2048         // GRU_OUT
#define FFND   2048
#define NE     8
#define GRU_CTAS 128

typedef unsigned long long u64;

// ---------------- packed fp32x2 helpers (FFMA2: PTX-only on sm_103a) ----------------
__device__ __forceinline__ u64 pk2(float x) {
    u64 r; asm("mov.b64 %0, {%1, %1};" : "=l"(r) : "f"(x)); return r;
}
__device__ __forceinline__ void fma2(u64& d, u64 a, u64 b) {
    asm("fma.rn.f32x2 %0, %1, %2, %0;" : "+l"(d) : "l"(a), "l"(b));
}
__device__ __forceinline__ float2 upk(u64 v) {
    float2 f; asm("mov.b64 {%0, %1}, %2;" : "=f"(f.x), "=f"(f.y) : "l"(v)); return f;
}

union F4U { float4 f; u64 u[2]; };

// ---------------- static device scratch ----------------
__device__ float g_xg[(size_t)NTOK * NWALL];      // x@Wih^T + bih, [token][dir*3H+row]
__device__ float g_wT[(size_t)DM * NWALL];        // Wih transposed
__device__ float g_flat[(size_t)NTOK * GOUT];     // leaky_relu(gru_out)
__device__ float g_h1[(size_t)NTOK * 2 * FFND];   // gelu per assignment row
__device__ float g_obuf[(size_t)NTOK * 2 * DM];   // per-assignment expert outputs
__device__ float g_hbuf[2][2][HH * BATCHN];       // ping-pong hidden state, [j][b] layout
__device__ int   g_list[NE][NTOK];
__device__ int   g_cnt[NE];
__device__ float g_wt[NTOK * 2];
__device__ float g_Psum[NE];
__device__ float g_zsum;
__device__ unsigned g_barcnt;
__device__ volatile unsigned g_bargen;

// ---------------- init ----------------
__global__ void init_kernel() {
    int i = blockIdx.x * blockDim.x + threadIdx.x;
    float* h0 = &g_hbuf[0][0][0];
    if (i < 2 * 2 * HH * BATCHN) h0[i] = 0.f;
    if (i < NE) { g_cnt[i] = 0; g_Psum[i] = 0.f; }
    if (i == 0) { g_zsum = 0.f; g_barcnt = 0u; g_bargen = 0u; }
}

// ---------------- transpose Wih [6144][512] -> g_wT [512][6144] ----------------
__global__ void transpose_w(const float* __restrict__ W) {
    __shared__ float tile[32][33];
    int k0 = blockIdx.x * 32, n0 = blockIdx.y * 32;
    int tx = threadIdx.x, ty = threadIdx.y;            // 32 x 8
    #pragma unroll
    for (int r = 0; r < 32; r += 8)
        tile[ty + r][tx] = W[(size_t)(n0 + ty + r) * DM + k0 + tx];
    __syncthreads();
    #pragma unroll
    for (int r = 0; r < 32; r += 8)
        g_wT[(size_t)(k0 + ty + r) * NWALL + n0 + tx] = tile[tx][ty + r];
}

// ---------------- 128x128x8 SGEMM, double-buffered, FFMA2 inner product ----------
// C[crow(m)][n] = sum_k A[arow(m)][k] * B[k][n] + bias[n]; optional gather + gelu.
__global__ void __launch_bounds__(256) gemm128(
    const float* __restrict__ A, int lda,
    const float* __restrict__ B, int ldb,
    const float* __restrict__ bias, int biasPerExp,
    float* __restrict__ C, int ldc,
    int M, int N, int K,
    int useList, int aDiv, int act, long bStride)
{
    const int* glist = nullptr;
    if (useList) {
        int e = blockIdx.z;
        M = g_cnt[e];
        glist = g_list[e];
        B += bStride * e;
        bias += (size_t)biasPerExp * e;
    }
    int m0 = blockIdx.y * 128;
    if (m0 >= M) return;
    int n0 = blockIdx.x * 128;

    __shared__ float As[2][8][128];
    __shared__ float Bs[2][8][128];

    int tid = threadIdx.x;
    int tx = tid & 15, ty = tid >> 4;
    int la_r = tid >> 1;            // A tile row (0..127)
    int la_k = (tid & 1) << 2;      // A tile k-offset (0 or 4)

    int mA = m0 + la_r;
    bool aValid = (mA < M);
    size_t arow = 0;
    if (aValid) {
        if (glist) { int gv = glist[mA]; arow = (size_t)(aDiv ? (gv >> 1) : gv); }
        else       arow = (size_t)mA;
    }
    const float* Aptr = A + arow * (size_t)lda + la_k;
    const float* Bptr = B + (size_t)(tid >> 5) * ldb + n0 + ((tid & 31) << 2);

    // acc[row][col-pair] packed over column pairs
    u64 acc[8][4];
    #pragma unroll
    for (int i = 0; i < 8; i++)
        #pragma unroll
        for (int j = 0; j < 4; j++) acc[i][j] = 0ull;

    // preload tile 0
    {
        float4 av = aValid ? *(const float4*)Aptr : make_float4(0.f,0.f,0.f,0.f);
        float4 bv = *(const float4*)Bptr;
        As[0][la_k + 0][la_r] = av.x; As[0][la_k + 1][la_r] = av.y;
        As[0][la_k + 2][la_r] = av.z; As[0][la_k + 3][la_r] = av.w;
        *(float4*)&Bs[0][tid >> 5][(tid & 31) << 2] = bv;
    }
    __syncthreads();

    int buf = 0;
    for (int k0 = 0; k0 < K; k0 += 8) {
        bool nxt = (k0 + 8 < K);
        float4 avn, bvn;
        if (nxt) {
            Aptr += 8;
            Bptr += (size_t)8 * ldb;
            avn = aValid ? *(const float4*)Aptr : make_float4(0.f,0.f,0.f,0.f);
            bvn = *(const float4*)Bptr;
        }
        #pragma unroll
        for (int kk = 0; kk < 8; kk++) {
            float4 a01 = *(const float4*)&As[buf][kk][ty * 8];
            float4 a23 = *(const float4*)&As[buf][kk][ty * 8 + 4];
            F4U b0, b1;
            b0.f = *(const float4*)&Bs[buf][kk][tx * 8];
            b1.f = *(const float4*)&Bs[buf][kk][tx * 8 + 4];
            float ra[8] = {a01.x, a01.y, a01.z, a01.w, a23.x, a23.y, a23.z, a23.w};
            #pragma unroll
            for (int i = 0; i < 8; i++) {
                u64 ai = pk2(ra[i]);
                fma2(acc[i][0], ai, b0.u[0]);
                fma2(acc[i][1], ai, b0.u[1]);
                fma2(acc[i][2], ai, b1.u[0]);
                fma2(acc[i][3], ai, b1.u[1]);
            }
        }
        if (nxt) {
            int ab = buf ^ 1;
            As[ab][la_k + 0][la_r] = avn.x; As[ab][la_k + 1][la_r] = avn.y;
            As[ab][la_k + 2][la_r] = avn.z; As[ab][la_k + 3][la_r] = avn.w;
            *(float4*)&Bs[ab][tid >> 5][(tid & 31) << 2] = bvn;
            __syncthreads();
            buf = ab;
        }
    }

    float bv[8];
    #pragma unroll
    for (int j = 0; j < 8; j++) bv[j] = bias[n0 + tx * 8 + j];

    #pragma unroll
    for (int i = 0; i < 8; i++) {
        int m = m0 + ty * 8 + i;
        if (m >= M) break;
        size_t crow = glist ? (size_t)glist[m] : (size_t)m;
        float* Cp = C + crow * (size_t)ldc + n0 + tx * 8;
        float v[8];
        #pragma unroll
        for (int jp = 0; jp < 4; jp++) {
            float2 p = upk(acc[i][jp]);
            v[2 * jp]     = p.x;
            v[2 * jp + 1] = p.y;
        }
        #pragma unroll
        for (int j = 0; j < 8; j++) {
            float t = v[j] + bv[j];
            if (act) t = 0.5f * t * (1.0f + erff(t * 0.70710678118654752f));
            v[j] = t;
        }
        *(float4*)Cp       = *(float4*)&v[0];
        *(float4*)(Cp + 4) = *(float4*)&v[4];
    }
}

// ---------------- software grid barrier (all CTAs co-resident) ----------------
__device__ __forceinline__ void grid_sync() {
    __syncthreads();
    if (threadIdx.x == 0) {
        __threadfence();
        unsigned gen = g_bargen;
        if (atomicAdd(&g_barcnt, 1u) == GRU_CTAS - 1) {
            g_barcnt = 0;
            __threadfence();
            g_bargen = gen + 1;
        } else {
            while (g_bargen == gen) __nanosleep(64);
        }
    }
    __syncthreads();
}

// ---------------- persistent bidirectional GRU (FFMA2 over batch pairs) --------
// 128 CTAs x 512 threads. Warp = hidden unit j of one direction.
// Hidden state stored [j][b] (batch contiguous) so batch pairs are packed f32x2.
__global__ void __launch_bounds__(512) gru_persist(
    const float* __restrict__ Whh, const float* __restrict__ bhh)
{
    __shared__ float hs[HH * BATCHN];   // 32 KB, [k][b]
    int bx = blockIdx.x;                // 0..127
    int dir = bx >> 6;
    int warp = threadIdx.x >> 5;        // 0..15
    int lane = threadIdx.x & 31;
    int j = (bx & 63) * 16 + warp;      // 0..1023

    const float* W0  = Whh + (size_t)dir * K3H * HH + (size_t)j * HH;
    const float* W1p = W0 + (size_t)HH * HH;
    const float* W2p = W0 + (size_t)2 * HH * HH;
    const float* bh  = bhh + dir * K3H;
    float bh_r = bh[j], bh_z = bh[HH + j], bh_n = bh[2 * HH + j];

    for (int s = 0; s < TLEN; s++) {
        int t = dir ? (TLEN - 1 - s) : s;
        const float4* hprev = (const float4*)&g_hbuf[s & 1][dir][0];
        float4* hs4 = (float4*)hs;
        #pragma unroll
        for (int idx = threadIdx.x; idx < HH * BATCHN / 4; idx += 512)
            hs4[idx] = __ldcg(&hprev[idx]);          // bypass L1 (stale-line hazard)
        __syncthreads();

        u64 a0[4], a1[4], a2[4];
        #pragma unroll
        for (int p = 0; p < 4; p++) { a0[p] = 0ull; a1[p] = 0ull; a2[p] = 0ull; }

        #pragma unroll
        for (int i = 0; i < 8; i++) {
            int kb = (lane << 2) + (i << 7);         // k base: 4 consecutive ks
            float4 w0v = *(const float4*)&W0[kb];
            float4 w1v = *(const float4*)&W1p[kb];
            float4 w2v = *(const float4*)&W2p[kb];
            float w0a[4] = {w0v.x, w0v.y, w0v.z, w0v.w};
            float w1a[4] = {w1v.x, w1v.y, w1v.z, w1v.w};
            float w2a[4] = {w2v.x, w2v.y, w2v.z, w2v.w};
            #pragma unroll
            for (int c = 0; c < 4; c++) {
                int k = kb + c;
                F4U hlo, hhi;
                hlo.f = *(const float4*)&hs[k * 8];      // batches 0..3
                hhi.f = *(const float4*)&hs[k * 8 + 4];  // batches 4..7
                u64 w0p = pk2(w0a[c]);
                u64 w1p_ = pk2(w1a[c]);
                u64 w2p_ = pk2(w2a[c]);
                fma2(a0[0], w0p, hlo.u[0]); fma2(a0[1], w0p, hlo.u[1]);
                fma2(a0[2], w0p, hhi.u[0]); fma2(a0[3], w0p, hhi.u[1]);
                fma2(a1[0], w1p_, hlo.u[0]); fma2(a1[1], w1p_, hlo.u[1]);
                fma2(a1[2], w1p_, hhi.u[0]); fma2(a1[3], w1p_, hhi.u[1]);
                fma2(a2[0], w2p_, hlo.u[0]); fma2(a2[1], w2p_, hlo.u[1]);
                fma2(a2[2], w2p_, hhi.u[0]); fma2(a2[3], w2p_, hhi.u[1]);
            }
        }

        // unpack to 24 scalars and butterfly-reduce across the warp
        float r0[8], r1[8], r2[8];
        #pragma unroll
        for (int p = 0; p < 4; p++) {
            float2 f0 = upk(a0[p]); r0[2*p] = f0.x; r0[2*p+1] = f0.y;
            float2 f1 = upk(a1[p]); r1[2*p] = f1.x; r1[2*p+1] = f1.y;
            float2 f2 = upk(a2[p]); r2[2*p] = f2.x; r2[2*p+1] = f2.y;
        }
        #pragma unroll
        for (int b = 0; b < 8; b++) {
            #pragma unroll
            for (int off = 16; off > 0; off >>= 1) {
                r0[b] += __shfl_xor_sync(0xffffffffu, r0[b], off);
                r1[b] += __shfl_xor_sync(0xffffffffu, r1[b], off);
                r2[b] += __shfl_xor_sync(0xffffffffu, r2[b], off);
            }
        }

        if (lane < 8) {
            int b = lane;
            int token = b * TLEN + t;
            const float* xgr = g_xg + (size_t)token * NWALL + (size_t)dir * K3H;
            float xr = xgr[j], xz = xgr[HH + j], xn = xgr[2 * HH + j];
            float hr = r0[b] + bh_r;
            float hz = r1[b] + bh_z;
            float hn = r2[b] + bh_n;
            float r  = 1.f / (1.f + expf(-(xr + hr)));
            float z  = 1.f / (1.f + expf(-(xz + hz)));
            float nn = tanhf(xn + r * hn);
            float hp = hs[j * 8 + b];
            float hnew = (1.f - z) * nn + z * hp;
            g_hbuf[(s + 1) & 1][dir][j * 8 + b] = hnew;
            g_flat[(size_t)token * GOUT + dir * HH + j] =
                hnew > 0.f ? hnew : 0.01f * hnew;
        }
        grid_sync();
    }
}

// ---------------- gating: warp per token ----------------
__global__ void gate_kernel(const float* __restrict__ gW, const float* __restrict__ gb) {
    int gwid = (blockIdx.x * blockDim.x + threadIdx.x) >> 5;
    int lane = threadIdx.x & 31;
    if (gwid >= NTOK) return;
    const float* f = g_flat + (size_t)gwid * GOUT;
    float acc[NE];
    #pragma unroll
    for (int e = 0; e < NE; e++) acc[e] = 0.f;
    for (int k = lane; k < GOUT; k += 32) {
        float fv = f[k];
        #pragma unroll
        for (int e = 0; e < NE; e++) acc[e] = fmaf(fv, gW[e * GOUT + k], acc[e]);
    }
    #pragma unroll
    for (int e = 0; e < NE; e++)
        #pragma unroll
        for (int off = 16; off > 0; off >>= 1)
            acc[e] += __shfl_xor_sync(0xffffffffu, acc[e], off);

    if (lane == 0) {
        float l[NE], mx = -1e30f;
        #pragma unroll
        for (int e = 0; e < NE; e++) { l[e] = acc[e] + gb[e]; mx = fmaxf(mx, l[e]); }
        float se = 0.f;
        #pragma unroll
        for (int e = 0; e < NE; e++) se += expf(l[e] - mx);
        float lse = mx + logf(se);
        float sc[NE];
        #pragma unroll
        for (int e = 0; e < NE; e++) sc[e] = expf(l[e] - lse);
        int e0 = 0; float s0 = sc[0];
        #pragma unroll
        for (int e = 1; e < NE; e++) if (sc[e] > s0) { s0 = sc[e]; e0 = e; }
        int e1 = -1; float s1 = -1e30f;
        #pragma unroll
        for (int e = 0; e < NE; e++) if (e != e0 && sc[e] > s1) { s1 = sc[e]; e1 = e; }
        float inv = 1.f / (s0 + s1);
        int p0 = atomicAdd(&g_cnt[e0], 1);
        g_list[e0][p0] = gwid * 2;
        int p1 = atomicAdd(&g_cnt[e1], 1);
        g_list[e1][p1] = gwid * 2 + 1;
        g_wt[gwid * 2]     = s0 * inv;
        g_wt[gwid * 2 + 1] = s1 * inv;
        atomicAdd(&g_zsum, lse * lse);
        #pragma unroll
        for (int e = 0; e < NE; e++) atomicAdd(&g_Psum[e], sc[e]);
    }
}

// ---------------- deterministic combine ----------------
__global__ void combine_kernel(float* __restrict__ out) {
    int idx = blockIdx.x * blockDim.x + threadIdx.x;
    if (idx >= NTOK * DM) return;
    int t = idx >> 9;
    int d = idx & (DM - 1);
    out[idx] = g_wt[2 * t]     * g_obuf[(size_t)(2 * t) * DM + d]
             + g_wt[2 * t + 1] * g_obuf[(size_t)(2 * t + 1) * DM + d];
}

// ---------------- aux loss scalar ----------------
__global__ void aux_kernel(float* out, int out_size) {
    if (out_size <= NTOK * DM) return;
    float s = 0.f;
    #pragma unroll
    for (int e = 0; e < NE; e++)
        s += ((float)g_cnt[e] / (float)NTOK) * (g_Psum[e] / (float)NTOK);
    out[NTOK * DM] = 0.01f * (float)NE * s + 0.001f * (g_zsum / (float)NTOK);
}

// ---------------- launch ----------------
extern "C" void kernel_launch(void* const* d_in, const int* in_sizes, int n_in,
                              void* d_out, int out_size) {
    const float* x   = (const float*)d_in[0];
    const float* Wih = (const float*)d_in[1];
    const float* Whh = (const float*)d_in[2];
    const float* bih = (const float*)d_in[3];
    const float* bhh = (const float*)d_in[4];
    const float* gW  = (const float*)d_in[5];
    const float* gb  = (const float*)d_in[6];
    const float* W1  = (const float*)d_in[7];
    const float* b1  = (const float*)d_in[8];
    const float* W2  = (const float*)d_in[9];
    const float* b2  = (const float*)d_in[10];
    float* out = (float*)d_out;

    float *p_xg, *p_flat, *p_h1, *p_obuf, *p_wT;
    cudaGetSymbolAddress((void**)&p_xg,   g_xg);
    cudaGetSymbolAddress((void**)&p_flat, g_flat);
    cudaGetSymbolAddress((void**)&p_h1,   g_h1);
    cudaGetSymbolAddress((void**)&p_obuf, g_obuf);
    cudaGetSymbolAddress((void**)&p_wT,   g_wT);

    init_kernel<<<256, 256>>>();
    transpose_w<<<dim3(16, 192), dim3(32, 8)>>>(Wih);

    // xg = x @ Wih^T + bih : M=8192, N=6144, K=512
    gemm128<<<dim3(48, 64, 1), 256>>>(x, DM, p_wT, NWALL, bih, 0,
                                      p_xg, NWALL, NTOK, NWALL, DM,
                                      0, 0, 0, 0L);

    // bidirectional GRU: one persistent kernel, software grid barrier per step
    gru_persist<<<GRU_CTAS, 512>>>(Whh, bhh);

    gate_kernel<<<NTOK / 8, 256>>>(gW, gb);

    // expert GEMM1 + GELU (gathered rows of flat)
    gemm128<<<dim3(16, 64, 8), 256>>>(p_flat, GOUT, W1, FFND, b1, FFND,
                                      p_h1, FFND, 0, FFND, GOUT,
                                      1, 1, 1, (long)GOUT * FFND);
    // expert GEMM2
    gemm128<<<dim3(4, 64, 8), 256>>>(p_h1, FFND, W2, DM, b2, DM,
                                     p_obuf, DM, 0, DM, FFND,
                                     1, 0, 0, (long)FFND * DM);

    combine_kernel<<<(NTOK * DM + 255) / 256, 256>>>(out);
    aux_kernel<<<1, 1>>>(out, out_size);
}

// round 5
// speedup vs baseline: 2.1174x; 2.1174x over previous
#include <cuda_runtime.h>
#include <math.h>

// ---------------- problem constants ----------------
#define BATCHN 8
#define TLEN   1024
#define DM     512          // D_MODEL
#define HH     1024         // H per direction
#define K3H    3072         // 3*H
#define NWALL  6144         // 2*3H  (both directions)
#define NTOK   8192         // B*T
#define GOUT   2048         // GRU_OUT
#define FFND   2048
#define NE     8
#define GRU_CTAS 128
#define GRU_SMEM ((16 * 3 * HH + BATCHN * HH) * 4)   // 229376 B

typedef unsigned long long u64;

// ---------------- packed fp32x2 helpers (FFMA2: PTX-only on sm_103a) ----------------
__device__ __forceinline__ u64 pk2(float x) {
    u64 r; asm("mov.b64 %0, {%1, %1};" : "=l"(r) : "f"(x)); return r;
}
__device__ __forceinline__ void fma2(u64& d, u64 a, u64 b) {
    asm("fma.rn.f32x2 %0, %1, %2, %0;" : "+l"(d) : "l"(a), "l"(b));
}
__device__ __forceinline__ float2 upk(u64 v) {
    float2 f; asm("mov.b64 {%0, %1}, %2;" : "=f"(f.x), "=f"(f.y) : "l"(v)); return f;
}

union F4U { float4 f; u64 u[2]; };

// ---------------- static device scratch ----------------
__device__ float g_xg[(size_t)NTOK * NWALL];      // x@Wih^T + bih
__device__ float g_wT[(size_t)DM * NWALL];        // Wih transposed
__device__ float g_flat[(size_t)NTOK * GOUT];     // leaky_relu(gru_out)
__device__ float g_h1[(size_t)NTOK * 2 * FFND];   // gelu per assignment row
__device__ float g_obuf[(size_t)NTOK * 2 * DM];   // per-assignment expert outputs
__device__ float g_hbuf[2][2][BATCHN * HH];       // ping-pong hidden state, [b][k]
__device__ int   g_list[NE][NTOK];
__device__ int   g_cnt[NE];
__device__ float g_wt[NTOK * 2];
__device__ float g_Psum[NE];
__device__ float g_zsum;
__device__ unsigned g_barcnt;
__device__ volatile unsigned g_bargen;

// ---------------- init ----------------
__global__ void init_kernel() {
    int i = blockIdx.x * blockDim.x + threadIdx.x;
    float* h0 = &g_hbuf[0][0][0];
    if (i < 2 * 2 * BATCHN * HH) h0[i] = 0.f;
    if (i < NE) { g_cnt[i] = 0; g_Psum[i] = 0.f; }
    if (i == 0) { g_zsum = 0.f; g_barcnt = 0u; g_bargen = 0u; }
}

// ---------------- transpose Wih [6144][512] -> g_wT [512][6144] ----------------
__global__ void transpose_w(const float* __restrict__ W) {
    __shared__ float tile[32][33];
    int k0 = blockIdx.x * 32, n0 = blockIdx.y * 32;
    int tx = threadIdx.x, ty = threadIdx.y;            // 32 x 8
    #pragma unroll
    for (int r = 0; r < 32; r += 8)
        tile[ty + r][tx] = W[(size_t)(n0 + ty + r) * DM + k0 + tx];
    __syncthreads();
    #pragma unroll
    for (int r = 0; r < 32; r += 8)
        g_wT[(size_t)(k0 + ty + r) * NWALL + n0 + tx] = tile[tx][ty + r];
}

// ---------------- 128x128x8 SGEMM, double-buffered, FFMA2 inner product ----------
__global__ void __launch_bounds__(256) gemm128(
    const float* __restrict__ A, int lda,
    const float* __restrict__ B, int ldb,
    const float* __restrict__ bias, int biasPerExp,
    float* __restrict__ C, int ldc,
    int M, int N, int K,
    int useList, int aDiv, int act, long bStride)
{
    const int* glist = nullptr;
    if (useList) {
        int e = blockIdx.z;
        M = g_cnt[e];
        glist = g_list[e];
        B += bStride * e;
        bias += (size_t)biasPerExp * e;
    }
    int m0 = blockIdx.y * 128;
    if (m0 >= M) return;
    int n0 = blockIdx.x * 128;

    __shared__ float As[2][8][128];
    __shared__ float Bs[2][8][128];

    int tid = threadIdx.x;
    int tx = tid & 15, ty = tid >> 4;
    int la_r = tid >> 1;
    int la_k = (tid & 1) << 2;

    int mA = m0 + la_r;
    bool aValid = (mA < M);
    size_t arow = 0;
    if (aValid) {
        if (glist) { int gv = glist[mA]; arow = (size_t)(aDiv ? (gv >> 1) : gv); }
        else       arow = (size_t)mA;
    }
    const float* Aptr = A + arow * (size_t)lda + la_k;
    const float* Bptr = B + (size_t)(tid >> 5) * ldb + n0 + ((tid & 31) << 2);

    u64 acc[8][4];
    #pragma unroll
    for (int i = 0; i < 8; i++)
        #pragma unroll
        for (int j = 0; j < 4; j++) acc[i][j] = 0ull;

    {
        float4 av = aValid ? *(const float4*)Aptr : make_float4(0.f,0.f,0.f,0.f);
        float4 bv = *(const float4*)Bptr;
        As[0][la_k + 0][la_r] = av.x; As[0][la_k + 1][la_r] = av.y;
        As[0][la_k + 2][la_r] = av.z; As[0][la_k + 3][la_r] = av.w;
        *(float4*)&Bs[0][tid >> 5][(tid & 31) << 2] = bv;
    }
    __syncthreads();

    int buf = 0;
    for (int k0 = 0; k0 < K; k0 += 8) {
        bool nxt = (k0 + 8 < K);
        float4 avn, bvn;
        if (nxt) {
            Aptr += 8;
            Bptr += (size_t)8 * ldb;
            avn = aValid ? *(const float4*)Aptr : make_float4(0.f,0.f,0.f,0.f);
            bvn = *(const float4*)Bptr;
        }
        #pragma unroll
        for (int kk = 0; kk < 8; kk++) {
            float4 a01 = *(const float4*)&As[buf][kk][ty * 8];
            float4 a23 = *(const float4*)&As[buf][kk][ty * 8 + 4];
            F4U b0, b1;
            b0.f = *(const float4*)&Bs[buf][kk][tx * 8];
            b1.f = *(const float4*)&Bs[buf][kk][tx * 8 + 4];
            float ra[8] = {a01.x, a01.y, a01.z, a01.w, a23.x, a23.y, a23.z, a23.w};
            #pragma unroll
            for (int i = 0; i < 8; i++) {
                u64 ai = pk2(ra[i]);
                fma2(acc[i][0], ai, b0.u[0]);
                fma2(acc[i][1], ai, b0.u[1]);
                fma2(acc[i][2], ai, b1.u[0]);
                fma2(acc[i][3], ai, b1.u[1]);
            }
        }
        if (nxt) {
            int ab = buf ^ 1;
            As[ab][la_k + 0][la_r] = avn.x; As[ab][la_k + 1][la_r] = avn.y;
            As[ab][la_k + 2][la_r] = avn.z; As[ab][la_k + 3][la_r] = avn.w;
            *(float4*)&Bs[ab][tid >> 5][(tid & 31) << 2] = bvn;
            __syncthreads();
            buf = ab;
        }
    }

    float bv[8];
    #pragma unroll
    for (int j = 0; j < 8; j++) bv[j] = bias[n0 + tx * 8 + j];

    #pragma unroll
    for (int i = 0; i < 8; i++) {
        int m = m0 + ty * 8 + i;
        if (m >= M) break;
        size_t crow = glist ? (size_t)glist[m] : (size_t)m;
        float* Cp = C + crow * (size_t)ldc + n0 + tx * 8;
        float v[8];
        #pragma unroll
        for (int jp = 0; jp < 4; jp++) {
            float2 p = upk(acc[i][jp]);
            v[2 * jp]     = p.x;
            v[2 * jp + 1] = p.y;
        }
        #pragma unroll
        for (int j = 0; j < 8; j++) {
            float t = v[j] + bv[j];
            if (act) t = 0.5f * t * (1.0f + erff(t * 0.70710678118654752f));
            v[j] = t;
        }
        *(float4*)Cp       = *(float4*)&v[0];
        *(float4*)(Cp + 4) = *(float4*)&v[4];
    }
}

// ---------------- software grid barrier (all CTAs co-resident) ----------------
__device__ __forceinline__ void grid_sync() {
    __syncthreads();
    if (threadIdx.x == 0) {
        __threadfence();
        unsigned gen = g_bargen;
        if (atomicAdd(&g_barcnt, 1u) == GRU_CTAS - 1) {
            g_barcnt = 0;
            __threadfence();
            g_bargen = gen + 1;
        } else {
            while (g_bargen == gen) __nanosleep(64);
        }
    }
    __syncthreads();
}

// ---------------- persistent bidirectional GRU --------------------------------
// 128 CTAs x 512 threads. Warp = hidden unit j of one direction.
// Whh slice (192KB) staged once in SMEM; hs in [b][k] layout (conflict-free
// LDS.64); FFMA2 packs k-pairs (lo/hi summed at the end).
__global__ void __launch_bounds__(512) gru_persist(
    const float* __restrict__ Whh, const float* __restrict__ bhh)
{
    extern __shared__ float smem[];
    float* sw = smem;                    // [16 warps][3 gates][1024]
    float* hs = smem + 16 * 3 * HH;      // [8][1024]
    int bx = blockIdx.x;
    int dir = bx >> 6;
    int warp = threadIdx.x >> 5;
    int lane = threadIdx.x & 31;
    int j = (bx & 63) * 16 + warp;

    // stage this warp's 3 Whh rows into SMEM (once, warp-local)
    {
        const float* Wb = Whh + (size_t)dir * K3H * HH;
        #pragma unroll
        for (int g = 0; g < 3; g++) {
            const float4* src = (const float4*)(Wb + (size_t)(g * HH + j) * HH);
            float4* dst = (float4*)(sw + (warp * 3 + g) * HH);
            #pragma unroll
            for (int kq = lane; kq < HH / 4; kq += 32)
                dst[kq] = src[kq];
        }
    }
    const float* bh = bhh + dir * K3H;
    float bh_r = bh[j], bh_z = bh[HH + j], bh_n = bh[2 * HH + j];

    const u64* w0 = (const u64*)(sw + warp * 3 * HH);   // gate r, k-pairs
    const u64* w1 = w0 + HH / 2;                        // gate z
    const u64* w2 = w1 + HH / 2;                        // gate n
    const u64* hp2 = (const u64*)hs;

    for (int s = 0; s < TLEN; s++) {
        int t = dir ? (TLEN - 1 - s) : s;
        const float4* hprev = (const float4*)&g_hbuf[s & 1][dir][0];
        float4* hs4 = (float4*)hs;
        #pragma unroll
        for (int idx = threadIdx.x; idx < BATCHN * HH / 4; idx += 512)
            hs4[idx] = __ldcg(&hprev[idx]);      // bypass L1 (stale-line hazard)
        __syncthreads();

        u64 a0[8], a1[8], a2[8];
        #pragma unroll
        for (int b = 0; b < 8; b++) { a0[b] = 0ull; a1[b] = 0ull; a2[b] = 0ull; }

        #pragma unroll 4
        for (int i = 0; i < 16; i++) {
            int kp = lane + i * 32;              // k-pair index 0..511
            u64 wr = w0[kp], wz = w1[kp], wn = w2[kp];
            #pragma unroll
            for (int b = 0; b < 8; b++) {
                u64 hv = hp2[b * (HH / 2) + kp];
                fma2(a0[b], wr, hv);
                fma2(a1[b], wz, hv);
                fma2(a2[b], wn, hv);
            }
        }

        float r0[8], r1[8], r2[8];
        #pragma unroll
        for (int b = 0; b < 8; b++) {
            float2 p;
            p = upk(a0[b]); r0[b] = p.x + p.y;
            p = upk(a1[b]); r1[b] = p.x + p.y;
            p = upk(a2[b]); r2[b] = p.x + p.y;
        }
        #pragma unroll
        for (int b = 0; b < 8; b++) {
            #pragma unroll
            for (int off = 16; off > 0; off >>= 1) {
                r0[b] += __shfl_xor_sync(0xffffffffu, r0[b], off);
                r1[b] += __shfl_xor_sync(0xffffffffu, r1[b], off);
                r2[b] += __shfl_xor_sync(0xffffffffu, r2[b], off);
            }
        }

        if (lane < 8) {
            int b = lane;
            int token = b * TLEN + t;
            const float* xgr = g_xg + (size_t)token * NWALL + (size_t)dir * K3H;
            float xr = xgr[j], xz = xgr[HH + j], xn = xgr[2 * HH + j];
            float hr = r0[b] + bh_r;
            float hz = r1[b] + bh_z;
            float hn = r2[b] + bh_n;
            float r  = 1.f / (1.f + expf(-(xr + hr)));
            float z  = 1.f / (1.f + expf(-(xz + hz)));
            float nn = tanhf(xn + r * hn);
            float hp = hs[b * HH + j];
            float hnew = (1.f - z) * nn + z * hp;
            g_hbuf[(s + 1) & 1][dir][b * HH + j] = hnew;
            g_flat[(size_t)token * GOUT + dir * HH + j] =
                hnew > 0.f ? hnew : 0.01f * hnew;
        }
        grid_sync();
    }
}

// ---------------- gating: warp per token ----------------
__global__ void gate_kernel(const float* __restrict__ gW, const float* __restrict__ gb) {
    int gwid = (blockIdx.x * blockDim.x + threadIdx.x) >> 5;
    int lane = threadIdx.x & 31;
    if (gwid >= NTOK) return;
    const float* f = g_flat + (size_t)gwid * GOUT;
    float acc[NE];
    #pragma unroll
    for (int e = 0; e < NE; e++) acc[e] = 0.f;
    for (int k = lane; k < GOUT; k += 32) {
        float fv = f[k];
        #pragma unroll
        for (int e = 0; e < NE; e++) acc[e] = fmaf(fv, gW[e * GOUT + k], acc[e]);
    }
    #pragma unroll
    for (int e = 0; e < NE; e++)
        #pragma unroll
        for (int off = 16; off > 0; off >>= 1)
            acc[e] += __shfl_xor_sync(0xffffffffu, acc[e], off);

    if (lane == 0) {
        float l[NE], mx = -1e30f;
        #pragma unroll
        for (int e = 0; e < NE; e++) { l[e] = acc[e] + gb[e]; mx = fmaxf(mx, l[e]); }
        float se = 0.f;
        #pragma unroll
        for (int e = 0; e < NE; e++) se += expf(l[e] - mx);
        float lse = mx + logf(se);
        float sc[NE];
        #pragma unroll
        for (int e = 0; e < NE; e++) sc[e] = expf(l[e] - lse);
        int e0 = 0; float s0 = sc[0];
        #pragma unroll
        for (int e = 1; e < NE; e++) if (sc[e] > s0) { s0 = sc[e]; e0 = e; }
        int e1 = -1; float s1 = -1e30f;
        #pragma unroll
        for (int e = 0; e < NE; e++) if (e != e0 && sc[e] > s1) { s1 = sc[e]; e1 = e; }
        float inv = 1.f / (s0 + s1);
        int p0 = atomicAdd(&g_cnt[e0], 1);
        g_list[e0][p0] = gwid * 2;
        int p1 = atomicAdd(&g_cnt[e1], 1);
        g_list[e1][p1] = gwid * 2 + 1;
        g_wt[gwid * 2]     = s0 * inv;
        g_wt[gwid * 2 + 1] = s1 * inv;
        atomicAdd(&g_zsum, lse * lse);
        #pragma unroll
        for (int e = 0; e < NE; e++) atomicAdd(&g_Psum[e], sc[e]);
    }
}

// ---------------- deterministic combine ----------------
__global__ void combine_kernel(float* __restrict__ out) {
    int idx = blockIdx.x * blockDim.x + threadIdx.x;
    if (idx >= NTOK * DM) return;
    int t = idx >> 9;
    int d = idx & (DM - 1);
    out[idx] = g_wt[2 * t]     * g_obuf[(size_t)(2 * t) * DM + d]
             + g_wt[2 * t + 1] * g_obuf[(size_t)(2 * t + 1) * DM + d];
}

// ---------------- aux loss scalar ----------------
__global__ void aux_kernel(float* out, int out_size) {
    if (out_size <= NTOK * DM) return;
    float s = 0.f;
    #pragma unroll
    for (int e = 0; e < NE; e++)
        s += ((float)g_cnt[e] / (float)NTOK) * (g_Psum[e] / (float)NTOK);
    out[NTOK * DM] = 0.01f * (float)NE * s + 0.001f * (g_zsum / (float)NTOK);
}

// ---------------- launch ----------------
extern "C" void kernel_launch(void* const* d_in, const int* in_sizes, int n_in,
                              void* d_out, int out_size) {
    const float* x   = (const float*)d_in[0];
    const float* Wih = (const float*)d_in[1];
    const float* Whh = (const float*)d_in[2];
    const float* bih = (const float*)d_in[3];
    const float* bhh = (const float*)d_in[4];
    const float* gW  = (const float*)d_in[5];
    const float* gb  = (const float*)d_in[6];
    const float* W1  = (const float*)d_in[7];
    const float* b1  = (const float*)d_in[8];
    const float* W2  = (const float*)d_in[9];
    const float* b2  = (const float*)d_in[10];
    float* out = (float*)d_out;

    float *p_xg, *p_flat, *p_h1, *p_obuf, *p_wT;
    cudaGetSymbolAddress((void**)&p_xg,   g_xg);
    cudaGetSymbolAddress((void**)&p_flat, g_flat);
    cudaGetSymbolAddress((void**)&p_h1,   g_h1);
    cudaGetSymbolAddress((void**)&p_obuf, g_obuf);
    cudaGetSymbolAddress((void**)&p_wT,   g_wT);

    cudaFuncSetAttribute(gru_persist,
                         cudaFuncAttributeMaxDynamicSharedMemorySize, GRU_SMEM);

    init_kernel<<<256, 256>>>();
    transpose_w<<<dim3(16, 192), dim3(32, 8)>>>(Wih);

    // xg = x @ Wih^T + bih : M=8192, N=6144, K=512
    gemm128<<<dim3(48, 64, 1), 256>>>(x, DM, p_wT, NWALL, bih, 0,
                                      p_xg, NWALL, NTOK, NWALL, DM,
                                      0, 0, 0, 0L);

    // bidirectional GRU: one persistent kernel, Whh SMEM-resident
    gru_persist<<<GRU_CTAS, 512, GRU_SMEM>>>(Whh, bhh);

    gate_kernel<<<NTOK / 8, 256>>>(gW, gb);

    // expert GEMM1 + GELU (gathered rows of flat)
    gemm128<<<dim3(16, 64, 8), 256>>>(p_flat, GOUT, W1, FFND, b1, FFND,
                                      p_h1, FFND, 0, FFND, GOUT,
                                      1, 1, 1, (long)GOUT * FFND);
    // expert GEMM2
    gemm128<<<dim3(4, 64, 8), 256>>>(p_h1, FFND, W2, DM, b2, DM,
                                     p_obuf, DM, 0, DM, FFND,
                                     1, 0, 0, (long)FFND * DM);

    combine_kernel<<<(NTOK * DM + 255) / 256, 256>>>(out);
    aux_kernel<<<1, 1>>>(out, out_size);
}

// round 6
// speedup vs baseline: 2.1432x; 1.0122x over previous
#include <cuda_runtime.h>
#include <math.h>

// ---------------- problem constants ----------------
#define BATCHN 8
#define TLEN   1024
#define DM     512          // D_MODEL
#define HH     1024         // H per direction
#define K3H    3072         // 3*H
#define NWALL  6144         // 2*3H  (both directions)
#define NTOK   8192         // B*T
#define GOUT   2048         // GRU_OUT
#define FFND   2048
#define NE     8
#define GRU_CTAS 128
#define GRU_SMEM ((16 * 3 * HH + BATCHN * HH) * 4)   // 229376 B

typedef unsigned long long u64;

// ---------------- packed fp32x2 helpers (FFMA2: PTX-only on sm_103a) ----------------
__device__ __forceinline__ u64 pk2(float x) {
    u64 r; asm("mov.b64 %0, {%1, %1};" : "=l"(r) : "f"(x)); return r;
}
__device__ __forceinline__ void fma2(u64& d, u64 a, u64 b) {
    asm("fma.rn.f32x2 %0, %1, %2, %0;" : "+l"(d) : "l"(a), "l"(b));
}
__device__ __forceinline__ float2 upk(u64 v) {
    float2 f; asm("mov.b64 {%0, %1}, %2;" : "=f"(f.x), "=f"(f.y) : "l"(v)); return f;
}

union F4U { float4 f; u64 u[2]; };

// ---------------- static device scratch ----------------
__device__ float g_xg[(size_t)NTOK * NWALL];      // x@Wih^T + bih
__device__ float g_wT[(size_t)DM * NWALL];        // Wih transposed
__device__ float g_flat[(size_t)NTOK * GOUT];     // leaky_relu(gru_out)
__device__ float g_h1[(size_t)NTOK * 2 * FFND];   // gelu per assignment row
__device__ float g_obuf[(size_t)NTOK * 2 * DM];   // per-assignment expert outputs
__device__ float g_hbuf[2][2][BATCHN * HH];       // ping-pong hidden state, [b][k]
__device__ int   g_list[NE][NTOK];
__device__ int   g_cnt[NE];
__device__ float g_wt[NTOK * 2];
__device__ float g_Psum[NE];
__device__ float g_zsum;
__device__ unsigned g_barcnt;
__device__ volatile unsigned g_bargen;

// ---------------- init ----------------
__global__ void init_kernel() {
    int i = blockIdx.x * blockDim.x + threadIdx.x;
    float* h0 = &g_hbuf[0][0][0];
    if (i < 2 * 2 * BATCHN * HH) h0[i] = 0.f;
    if (i < NE) { g_cnt[i] = 0; g_Psum[i] = 0.f; }
    if (i == 0) { g_zsum = 0.f; g_barcnt = 0u; g_bargen = 0u; }
}

// ---------------- transpose Wih [6144][512] -> g_wT [512][6144] ----------------
__global__ void transpose_w(const float* __restrict__ W) {
    __shared__ float tile[32][33];
    int k0 = blockIdx.x * 32, n0 = blockIdx.y * 32;
    int tx = threadIdx.x, ty = threadIdx.y;            // 32 x 8
    #pragma unroll
    for (int r = 0; r < 32; r += 8)
        tile[ty + r][tx] = W[(size_t)(n0 + ty + r) * DM + k0 + tx];
    __syncthreads();
    #pragma unroll
    for (int r = 0; r < 32; r += 8)
        g_wT[(size_t)(k0 + ty + r) * NWALL + n0 + tx] = tile[tx][ty + r];
}

// ---------------- 128x128x8 SGEMM, double-buffered, FFMA2 inner product ----------
__global__ void __launch_bounds__(256) gemm128(
    const float* __restrict__ A, int lda,
    const float* __restrict__ B, int ldb,
    const float* __restrict__ bias, int biasPerExp,
    float* __restrict__ C, int ldc,
    int M, int N, int K,
    int useList, int aDiv, int act, long bStride)
{
    const int* glist = nullptr;
    if (useList) {
        int e = blockIdx.z;
        M = g_cnt[e];
        glist = g_list[e];
        B += bStride * e;
        bias += (size_t)biasPerExp * e;
    }
    int m0 = blockIdx.y * 128;
    if (m0 >= M) return;
    int n0 = blockIdx.x * 128;

    __shared__ float As[2][8][128];
    __shared__ float Bs[2][8][128];

    int tid = threadIdx.x;
    int tx = tid & 15, ty = tid >> 4;
    int la_r = tid >> 1;
    int la_k = (tid & 1) << 2;

    int mA = m0 + la_r;
    bool aValid = (mA < M);
    size_t arow = 0;
    if (aValid) {
        if (glist) { int gv = glist[mA]; arow = (size_t)(aDiv ? (gv >> 1) : gv); }
        else       arow = (size_t)mA;
    }
    const float* Aptr = A + arow * (size_t)lda + la_k;
    const float* Bptr = B + (size_t)(tid >> 5) * ldb + n0 + ((tid & 31) << 2);

    u64 acc[8][4];
    #pragma unroll
    for (int i = 0; i < 8; i++)
        #pragma unroll
        for (int j = 0; j < 4; j++) acc[i][j] = 0ull;

    {
        float4 av = aValid ? *(const float4*)Aptr : make_float4(0.f,0.f,0.f,0.f);
        float4 bv = *(const float4*)Bptr;
        As[0][la_k + 0][la_r] = av.x; As[0][la_k + 1][la_r] = av.y;
        As[0][la_k + 2][la_r] = av.z; As[0][la_k + 3][la_r] = av.w;
        *(float4*)&Bs[0][tid >> 5][(tid & 31) << 2] = bv;
    }
    __syncthreads();

    int buf = 0;
    for (int k0 = 0; k0 < K; k0 += 8) {
        bool nxt = (k0 + 8 < K);
        float4 avn, bvn;
        if (nxt) {
            Aptr += 8;
            Bptr += (size_t)8 * ldb;
            avn = aValid ? *(const float4*)Aptr : make_float4(0.f,0.f,0.f,0.f);
            bvn = *(const float4*)Bptr;
        }
        #pragma unroll
        for (int kk = 0; kk < 8; kk++) {
            float4 a01 = *(const float4*)&As[buf][kk][ty * 8];
            float4 a23 = *(const float4*)&As[buf][kk][ty * 8 + 4];
            F4U b0, b1;
            b0.f = *(const float4*)&Bs[buf][kk][tx * 8];
            b1.f = *(const float4*)&Bs[buf][kk][tx * 8 + 4];
            float ra[8] = {a01.x, a01.y, a01.z, a01.w, a23.x, a23.y, a23.z, a23.w};
            #pragma unroll
            for (int i = 0; i < 8; i++) {
                u64 ai = pk2(ra[i]);
                fma2(acc[i][0], ai, b0.u[0]);
                fma2(acc[i][1], ai, b0.u[1]);
                fma2(acc[i][2], ai, b1.u[0]);
                fma2(acc[i][3], ai, b1.u[1]);
            }
        }
        if (nxt) {
            int ab = buf ^ 1;
            As[ab][la_k + 0][la_r] = avn.x; As[ab][la_k + 1][la_r] = avn.y;
            As[ab][la_k + 2][la_r] = avn.z; As[ab][la_k + 3][la_r] = avn.w;
            *(float4*)&Bs[ab][tid >> 5][(tid & 31) << 2] = bvn;
            __syncthreads();
            buf = ab;
        }
    }

    float bv[8];
    #pragma unroll
    for (int j = 0; j < 8; j++) bv[j] = bias[n0 + tx * 8 + j];

    #pragma unroll
    for (int i = 0; i < 8; i++) {
        int m = m0 + ty * 8 + i;
        if (m >= M) break;
        size_t crow = glist ? (size_t)glist[m] : (size_t)m;
        float* Cp = C + crow * (size_t)ldc + n0 + tx * 8;
        float v[8];
        #pragma unroll
        for (int jp = 0; jp < 4; jp++) {
            float2 p = upk(acc[i][jp]);
            v[2 * jp]     = p.x;
            v[2 * jp + 1] = p.y;
        }
        #pragma unroll
        for (int j = 0; j < 8; j++) {
            float t = v[j] + bv[j];
            if (act) t = 0.5f * t * (1.0f + erff(t * 0.70710678118654752f));
            v[j] = t;
        }
        *(float4*)Cp       = *(float4*)&v[0];
        *(float4*)(Cp + 4) = *(float4*)&v[4];
    }
}

// ---------------- software grid barrier (all CTAs co-resident) ----------------
__device__ __forceinline__ void grid_sync() {
    __syncthreads();
    if (threadIdx.x == 0) {
        __threadfence();
        unsigned gen = g_bargen;
        if (atomicAdd(&g_barcnt, 1u) == GRU_CTAS - 1) {
            g_barcnt = 0;
            __threadfence();
            g_bargen = gen + 1;
        } else {
            while (g_bargen == gen) __nanosleep(64);
        }
    }
    __syncthreads();
}

// ---------------- persistent bidirectional GRU --------------------------------
// 128 CTAs x 512 threads. Warp = hidden unit j of one direction.
// Whh slice (192KB) SMEM-resident; hs [b][k] (conflict-free LDS.128);
// FFMA2 packs k-pairs; LDS.128 for weights and h; xg prefetched per step.
__global__ void __launch_bounds__(512) gru_persist(
    const float* __restrict__ Whh, const float* __restrict__ bhh)
{
    extern __shared__ float smem[];
    float* sw = smem;                    // [16 warps][3 gates][1024]
    float* hs = smem + 16 * 3 * HH;      // [8][1024]
    int bx = blockIdx.x;
    int dir = bx >> 6;
    int warp = threadIdx.x >> 5;
    int lane = threadIdx.x & 31;
    int j = (bx & 63) * 16 + warp;

    // stage this warp's 3 Whh rows into SMEM (once)
    {
        const float* Wb = Whh + (size_t)dir * K3H * HH;
        #pragma unroll
        for (int g = 0; g < 3; g++) {
            const float4* src = (const float4*)(Wb + (size_t)(g * HH + j) * HH);
            float4* dst = (float4*)(sw + (warp * 3 + g) * HH);
            #pragma unroll
            for (int kq = lane; kq < HH / 4; kq += 32)
                dst[kq] = src[kq];
        }
    }
    const float* bh = bhh + dir * K3H;
    float bh_r = bh[j], bh_z = bh[HH + j], bh_n = bh[2 * HH + j];

    const F4U* w0_4 = (const F4U*)(sw + warp * 3 * HH);   // gate r, float4 = 2 k-pairs
    const F4U* w1_4 = w0_4 + HH / 4;                      // gate z
    const F4U* w2_4 = w1_4 + HH / 4;                      // gate n
    const F4U* h4   = (const F4U*)hs;

    for (int s = 0; s < TLEN; s++) {
        int t = dir ? (TLEN - 1 - s) : s;

        // prefetch this step's gate inputs (overlaps copy + compute)
        float xr = 0.f, xz = 0.f, xn = 0.f;
        if (lane < 8) {
            const float* xgr = g_xg + (size_t)(lane * TLEN + t) * NWALL
                                    + (size_t)dir * K3H;
            xr = __ldg(&xgr[j]);
            xz = __ldg(&xgr[HH + j]);
            xn = __ldg(&xgr[2 * HH + j]);
        }

        const float4* hprev = (const float4*)&g_hbuf[s & 1][dir][0];
        float4* hs4 = (float4*)hs;
        #pragma unroll
        for (int idx = threadIdx.x; idx < BATCHN * HH / 4; idx += 512)
            hs4[idx] = __ldcg(&hprev[idx]);      // bypass L1 (stale-line hazard)
        __syncthreads();

        u64 a0[8], a1[8], a2[8];
        #pragma unroll
        for (int b = 0; b < 8; b++) { a0[b] = 0ull; a1[b] = 0ull; a2[b] = 0ull; }

        #pragma unroll 4
        for (int i = 0; i < 8; i++) {
            int kq = lane + (i << 5);            // float4 index (2 k-pairs)
            F4U wr = w0_4[kq];
            F4U wz = w1_4[kq];
            F4U wn = w2_4[kq];
            #pragma unroll
            for (int b = 0; b < 8; b++) {
                F4U hv = h4[b * (HH / 4) + kq];
                fma2(a0[b], wr.u[0], hv.u[0]);
                fma2(a1[b], wz.u[0], hv.u[0]);
                fma2(a2[b], wn.u[0], hv.u[0]);
                fma2(a0[b], wr.u[1], hv.u[1]);
                fma2(a1[b], wz.u[1], hv.u[1]);
                fma2(a2[b], wn.u[1], hv.u[1]);
            }
        }

        float r0[8], r1[8], r2[8];
        #pragma unroll
        for (int b = 0; b < 8; b++) {
            float2 p;
            p = upk(a0[b]); r0[b] = p.x + p.y;
            p = upk(a1[b]); r1[b] = p.x + p.y;
            p = upk(a2[b]); r2[b] = p.x + p.y;
        }
        #pragma unroll
        for (int b = 0; b < 8; b++) {
            #pragma unroll
            for (int off = 16; off > 0; off >>= 1) {
                r0[b] += __shfl_xor_sync(0xffffffffu, r0[b], off);
                r1[b] += __shfl_xor_sync(0xffffffffu, r1[b], off);
                r2[b] += __shfl_xor_sync(0xffffffffu, r2[b], off);
            }
        }

        if (lane < 8) {
            int b = lane;
            int token = b * TLEN + t;
            float hr = r0[b] + bh_r;
            float hz = r1[b] + bh_z;
            float hn = r2[b] + bh_n;
            float r  = 1.f / (1.f + expf(-(xr + hr)));
            float z  = 1.f / (1.f + expf(-(xz + hz)));
            float nn = tanhf(xn + r * hn);
            float hp = hs[b * HH + j];
            float hnew = (1.f - z) * nn + z * hp;
            g_hbuf[(s + 1) & 1][dir][b * HH + j] = hnew;
            g_flat[(size_t)token * GOUT + dir * HH + j] =
                hnew > 0.f ? hnew : 0.01f * hnew;
        }
        grid_sync();
    }
}

// ---------------- gating: warp per token ----------------
__global__ void gate_kernel(const float* __restrict__ gW, const float* __restrict__ gb) {
    int gwid = (blockIdx.x * blockDim.x + threadIdx.x) >> 5;
    int lane = threadIdx.x & 31;
    if (gwid >= NTOK) return;
    const float* f = g_flat + (size_t)gwid * GOUT;
    float acc[NE];
    #pragma unroll
    for (int e = 0; e < NE; e++) acc[e] = 0.f;
    for (int k = lane; k < GOUT; k += 32) {
        float fv = f[k];
        #pragma unroll
        for (int e = 0; e < NE; e++) acc[e] = fmaf(fv, gW[e * GOUT + k], acc[e]);
    }
    #pragma unroll
    for (int e = 0; e < NE; e++)
        #pragma unroll
        for (int off = 16; off > 0; off >>= 1)
            acc[e] += __shfl_xor_sync(0xffffffffu, acc[e], off);

    if (lane == 0) {
        float l[NE], mx = -1e30f;
        #pragma unroll
        for (int e = 0; e < NE; e++) { l[e] = acc[e] + gb[e]; mx = fmaxf(mx, l[e]); }
        float se = 0.f;
        #pragma unroll
        for (int e = 0; e < NE; e++) se += expf(l[e] - mx);
        float lse = mx + logf(se);
        float sc[NE];
        #pragma unroll
        for (int e = 0; e < NE; e++) sc[e] = expf(l[e] - lse);
        int e0 = 0; float s0 = sc[0];
        #pragma unroll
        for (int e = 1; e < NE; e++) if (sc[e] > s0) { s0 = sc[e]; e0 = e; }
        int e1 = -1; float s1 = -1e30f;
        #pragma unroll
        for (int e = 0; e < NE; e++) if (e != e0 && sc[e] > s1) { s1 = sc[e]; e1 = e; }
        float inv = 1.f / (s0 + s1);
        int p0 = atomicAdd(&g_cnt[e0], 1);
        g_list[e0][p0] = gwid * 2;
        int p1 = atomicAdd(&g_cnt[e1], 1);
        g_list[e1][p1] = gwid * 2 + 1;
        g_wt[gwid * 2]     = s0 * inv;
        g_wt[gwid * 2 + 1] = s1 * inv;
        atomicAdd(&g_zsum, lse * lse);
        #pragma unroll
        for (int e = 0; e < NE; e++) atomicAdd(&g_Psum[e], sc[e]);
    }
}

// ---------------- deterministic combine ----------------
__global__ void combine_kernel(float* __restrict__ out) {
    int idx = blockIdx.x * blockDim.x + threadIdx.x;
    if (idx >= NTOK * DM) return;
    int t = idx >> 9;
    int d = idx & (DM - 1);
    out[idx] = g_wt[2 * t]     * g_obuf[(size_t)(2 * t) * DM + d]
             + g_wt[2 * t + 1] * g_obuf[(size_t)(2 * t + 1) * DM + d];
}

// ---------------- aux loss scalar ----------------
__global__ void aux_kernel(float* out, int out_size) {
    if (out_size <= NTOK * DM) return;
    float s = 0.f;
    #pragma unroll
    for (int e = 0; e < NE; e++)
        s += ((float)g_cnt[e] / (float)NTOK) * (g_Psum[e] / (float)NTOK);
    out[NTOK * DM] = 0.01f * (float)NE * s + 0.001f * (g_zsum / (float)NTOK);
}

// ---------------- launch ----------------
extern "C" void kernel_launch(void* const* d_in, const int* in_sizes, int n_in,
                              void* d_out, int out_size) {
    const float* x   = (const float*)d_in[0];
    const float* Wih = (const float*)d_in[1];
    const float* Whh = (const float*)d_in[2];
    const float* bih = (const float*)d_in[3];
    const float* bhh = (const float*)d_in[4];
    const float* gW  = (const float*)d_in[5];
    const float* gb  = (const float*)d_in[6];
    const float* W1  = (const float*)d_in[7];
    const float* b1  = (const float*)d_in[8];
    const float* W2  = (const float*)d_in[9];
    const float* b2  = (const float*)d_in[10];
    float* out = (float*)d_out;

    float *p_xg, *p_flat, *p_h1, *p_obuf, *p_wT;
    cudaGetSymbolAddress((void**)&p_xg,   g_xg);
    cudaGetSymbolAddress((void**)&p_flat, g_flat);
    cudaGetSymbolAddress((void**)&p_h1,   g_h1);
    cudaGetSymbolAddress((void**)&p_obuf, g_obuf);
    cudaGetSymbolAddress((void**)&p_wT,   g_wT);

    cudaFuncSetAttribute(gru_persist,
                         cudaFuncAttributeMaxDynamicSharedMemorySize, GRU_SMEM);

    init_kernel<<<256, 256>>>();
    transpose_w<<<dim3(16, 192), dim3(32, 8)>>>(Wih);

    // xg = x @ Wih^T + bih : M=8192, N=6144, K=512
    gemm128<<<dim3(48, 64, 1), 256>>>(x, DM, p_wT, NWALL, bih, 0,
                                      p_xg, NWALL, NTOK, NWALL, DM,
                                      0, 0, 0, 0L);

    // bidirectional GRU: one persistent kernel, Whh SMEM-resident
    gru_persist<<<GRU_CTAS, 512, GRU_SMEM>>>(Whh, bhh);

    gate_kernel<<<NTOK / 8, 256>>>(gW, gb);

    // expert GEMM1 + GELU (gathered rows of flat)
    gemm128<<<dim3(16, 64, 8), 256>>>(p_flat, GOUT, W1, FFND, b1, FFND,
                                      p_h1, FFND, 0, FFND, GOUT,
                                      1, 1, 1, (long)GOUT * FFND);
    // expert GEMM2
    gemm128<<<dim3(4, 64, 8), 256>>>(p_h1, FFND, W2, DM, b2, DM,
                                     p_obuf, DM, 0, DM, FFND,
                                     1, 0, 0, (long)FFND * DM);

    combine_kernel<<<(NTOK * DM + 255) / 256, 256>>>(out);
    aux_kernel<<<1, 1>>>(out, out_size);
}

// round 7
// speedup vs baseline: 2.2082x; 1.0303x over previous
#include <cuda_runtime.h>
#include <math.h>

// ---------------- problem constants ----------------
#define BATCHN 8
#define TLEN   1024
#define DM     512          // D_MODEL
#define HH     1024         // H per direction
#define K3H    3072         // 3*H
#define NWALL  6144         // 2*3H  (both directions)
#define NTOK   8192         // B*T
#define GOUT   2048         // GRU_OUT
#define FFND   2048
#define NE     8
#define GRU_CTAS 128
#define DIR_CTAS 64
// weights 192KB + hs 32KB + sred 3KB = 232448 B (== 227KB dynamic max)
#define GRU_SMEM ((16 * 3 * HH + BATCHN * HH + 16 * 48) * 4)

typedef unsigned long long u64;

// ---------------- packed fp32x2 helpers (FFMA2: PTX-only on sm_103a) ----------------
__device__ __forceinline__ u64 pk2(float x) {
    u64 r; asm("mov.b64 %0, {%1, %1};" : "=l"(r) : "f"(x)); return r;
}
__device__ __forceinline__ void fma2(u64& d, u64 a, u64 b) {
    asm("fma.rn.f32x2 %0, %1, %2, %0;" : "+l"(d) : "l"(a), "l"(b));
}
__device__ __forceinline__ float2 upk(u64 v) {
    float2 f; asm("mov.b64 {%0, %1}, %2;" : "=f"(f.x), "=f"(f.y) : "l"(v)); return f;
}

union F4U { float4 f; u64 u[2]; };

// ---------------- static device scratch ----------------
__device__ float g_xg[(size_t)NTOK * NWALL];      // x@Wih^T + bih
__device__ float g_wT[(size_t)DM * NWALL];        // Wih transposed
__device__ float g_flat[(size_t)NTOK * GOUT];     // leaky_relu(gru_out)
__device__ float g_h1[(size_t)NTOK * 2 * FFND];   // gelu per assignment row
__device__ float g_obuf[(size_t)NTOK * 2 * DM];   // per-assignment expert outputs
__device__ float g_hbuf[2][2][BATCHN * HH];       // ping-pong hidden state, [b][k]
__device__ int   g_list[NE][NTOK];
__device__ int   g_cnt[NE];
__device__ float g_wt[NTOK * 2];
__device__ float g_Psum[NE];
__device__ float g_zsum;
__device__ unsigned g_barcnt[2];
__device__ volatile unsigned g_bargen[2];

// ---------------- init ----------------
__global__ void init_kernel() {
    int i = blockIdx.x * blockDim.x + threadIdx.x;
    float* h0 = &g_hbuf[0][0][0];
    if (i < 2 * 2 * BATCHN * HH) h0[i] = 0.f;
    if (i < NE) { g_cnt[i] = 0; g_Psum[i] = 0.f; }
    if (i < 2) { g_barcnt[i] = 0u; g_bargen[i] = 0u; }
    if (i == 0) g_zsum = 0.f;
}

// ---------------- transpose Wih [6144][512] -> g_wT [512][6144] ----------------
__global__ void transpose_w(const float* __restrict__ W) {
    __shared__ float tile[32][33];
    int k0 = blockIdx.x * 32, n0 = blockIdx.y * 32;
    int tx = threadIdx.x, ty = threadIdx.y;            // 32 x 8
    #pragma unroll
    for (int r = 0; r < 32; r += 8)
        tile[ty + r][tx] = W[(size_t)(n0 + ty + r) * DM + k0 + tx];
    __syncthreads();
    #pragma unroll
    for (int r = 0; r < 32; r += 8)
        g_wT[(size_t)(k0 + ty + r) * NWALL + n0 + tx] = tile[tx][ty + r];
}

// ---------------- 128x128x8 SGEMM, double-buffered, FFMA2 inner product ----------
__global__ void __launch_bounds__(256) gemm128(
    const float* __restrict__ A, int lda,
    const float* __restrict__ B, int ldb,
    const float* __restrict__ bias, int biasPerExp,
    float* __restrict__ C, int ldc,
    int M, int N, int K,
    int useList, int aDiv, int act, long bStride)
{
    const int* glist = nullptr;
    if (useList) {
        int e = blockIdx.z;
        M = g_cnt[e];
        glist = g_list[e];
        B += bStride * e;
        bias += (size_t)biasPerExp * e;
    }
    int m0 = blockIdx.y * 128;
    if (m0 >= M) return;
    int n0 = blockIdx.x * 128;

    __shared__ float As[2][8][128];
    __shared__ float Bs[2][8][128];

    int tid = threadIdx.x;
    int tx = tid & 15, ty = tid >> 4;
    int la_r = tid >> 1;
    int la_k = (tid & 1) << 2;

    int mA = m0 + la_r;
    bool aValid = (mA < M);
    size_t arow = 0;
    if (aValid) {
        if (glist) { int gv = glist[mA]; arow = (size_t)(aDiv ? (gv >> 1) : gv); }
        else       arow = (size_t)mA;
    }
    const float* Aptr = A + arow * (size_t)lda + la_k;
    const float* Bptr = B + (size_t)(tid >> 5) * ldb + n0 + ((tid & 31) << 2);

    u64 acc[8][4];
    #pragma unroll
    for (int i = 0; i < 8; i++)
        #pragma unroll
        for (int j = 0; j < 4; j++) acc[i][j] = 0ull;

    {
        float4 av = aValid ? *(const float4*)Aptr : make_float4(0.f,0.f,0.f,0.f);
        float4 bv = *(const float4*)Bptr;
        As[0][la_k + 0][la_r] = av.x; As[0][la_k + 1][la_r] = av.y;
        As[0][la_k + 2][la_r] = av.z; As[0][la_k + 3][la_r] = av.w;
        *(float4*)&Bs[0][tid >> 5][(tid & 31) << 2] = bv;
    }
    __syncthreads();

    int buf = 0;
    for (int k0 = 0; k0 < K; k0 += 8) {
        bool nxt = (k0 + 8 < K);
        float4 avn, bvn;
        if (nxt) {
            Aptr += 8;
            Bptr += (size_t)8 * ldb;
            avn = aValid ? *(const float4*)Aptr : make_float4(0.f,0.f,0.f,0.f);
            bvn = *(const float4*)Bptr;
        }
        #pragma unroll
        for (int kk = 0; kk < 8; kk++) {
            float4 a01 = *(const float4*)&As[buf][kk][ty * 8];
            float4 a23 = *(const float4*)&As[buf][kk][ty * 8 + 4];
            F4U b0, b1;
            b0.f = *(const float4*)&Bs[buf][kk][tx * 8];
            b1.f = *(const float4*)&Bs[buf][kk][tx * 8 + 4];
            float ra[8] = {a01.x, a01.y, a01.z, a01.w, a23.x, a23.y, a23.z, a23.w};
            #pragma unroll
            for (int i = 0; i < 8; i++) {
                u64 ai = pk2(ra[i]);
                fma2(acc[i][0], ai, b0.u[0]);
                fma2(acc[i][1], ai, b0.u[1]);
                fma2(acc[i][2], ai, b1.u[0]);
                fma2(acc[i][3], ai, b1.u[1]);
            }
        }
        if (nxt) {
            int ab = buf ^ 1;
            As[ab][la_k + 0][la_r] = avn.x; As[ab][la_k + 1][la_r] = avn.y;
            As[ab][la_k + 2][la_r] = avn.z; As[ab][la_k + 3][la_r] = avn.w;
            *(float4*)&Bs[ab][tid >> 5][(tid & 31) << 2] = bvn;
            __syncthreads();
            buf = ab;
        }
    }

    float bv[8];
    #pragma unroll
    for (int j = 0; j < 8; j++) bv[j] = bias[n0 + tx * 8 + j];

    #pragma unroll
    for (int i = 0; i < 8; i++) {
        int m = m0 + ty * 8 + i;
        if (m >= M) break;
        size_t crow = glist ? (size_t)glist[m] : (size_t)m;
        float* Cp = C + crow * (size_t)ldc + n0 + tx * 8;
        float v[8];
        #pragma unroll
        for (int jp = 0; jp < 4; jp++) {
            float2 p = upk(acc[i][jp]);
            v[2 * jp]     = p.x;
            v[2 * jp + 1] = p.y;
        }
        #pragma unroll
        for (int j = 0; j < 8; j++) {
            float t = v[j] + bv[j];
            if (act) t = 0.5f * t * (1.0f + erff(t * 0.70710678118654752f));
            v[j] = t;
        }
        *(float4*)Cp       = *(float4*)&v[0];
        *(float4*)(Cp + 4) = *(float4*)&v[4];
    }
}

// ---------------- per-direction grid barrier (64 CTAs co-resident) -------------
__device__ __forceinline__ void grid_sync_dir(int dir) {
    __syncthreads();
    if (threadIdx.x == 0) {
        __threadfence();
        unsigned gen = g_bargen[dir];
        if (atomicAdd(&g_barcnt[dir], 1u) == DIR_CTAS - 1) {
            g_barcnt[dir] = 0;
            __threadfence();
            g_bargen[dir] = gen + 1;
        } else {
            while (g_bargen[dir] == gen) __nanosleep(64);
        }
    }
    __syncthreads();
}

// ---------------- persistent bidirectional GRU --------------------------------
// 128 CTAs x 512 threads. CTA owns 16 hidden units j of one direction.
// warp = (khalf, jpair): 2 j's over half the k range  -> hs crossbar traffic /2.
// lane = (bh, kg): 2 batch-halves x 16 interleaved k-groups (conflict-free,
// w reads broadcast across bh pairs). Cross-khalf combine via 3KB SMEM buffer.
__global__ void __launch_bounds__(512) gru_persist(
    const float* __restrict__ Whh, const float* __restrict__ bhh)
{
    extern __shared__ float smem[];
    float* sw   = smem;                              // [16 jj][3 g][1024]
    float* hs   = smem + 16 * 3 * HH;                // [8][1024]
    float* sred = smem + 16 * 3 * HH + BATCHN * HH;  // [16 warp][48]
    int bx = blockIdx.x;
    int dir = bx >> 6;
    int warp = threadIdx.x >> 5;
    int lane = threadIdx.x & 31;

    int khalf = warp >> 3;          // 0/1: k in [khalf*512, +512)
    int wp    = warp & 7;           // j-pair id: j = 2wp, 2wp+1
    int bh    = lane >> 4;          // batch half: b in [bh*4, +4)
    int kg    = lane & 15;          // k-group

    // stage weights (once): warp w loads jj=w's 3 gate rows
    {
        int jglob = (bx & 63) * 16 + warp;
        const float* Wb = Whh + (size_t)dir * K3H * HH;
        #pragma unroll
        for (int g = 0; g < 3; g++) {
            const float4* src = (const float4*)(Wb + (size_t)(g * HH + jglob) * HH);
            float4* dst = (float4*)(sw + (warp * 3 + g) * HH);
            for (int kq = lane; kq < HH / 4; kq += 32)
                dst[kq] = src[kq];
        }
    }

    // tail role: warps 0-7, lanes 0-15 handle (jj = wp*2 + (lane>>3), b = lane&7)
    bool tail = (warp < 8) && (lane < 16);
    int tjj = wp * 2 + (lane >> 3);
    int tb  = lane & 7;
    int tj  = (bx & 63) * 16 + tjj;          // j within direction
    float bh_r = 0.f, bh_z = 0.f, bh_n = 0.f;
    if (tail) {
        const float* bhp = bhh + dir * K3H;
        bh_r = bhp[tj]; bh_z = bhp[HH + tj]; bh_n = bhp[2 * HH + tj];
    }

    const F4U* wA[3];
    const F4U* wB[3];
    #pragma unroll
    for (int g = 0; g < 3; g++) {
        wA[g] = (const F4U*)(sw + ((wp * 2 + 0) * 3 + g) * HH);
        wB[g] = (const F4U*)(sw + ((wp * 2 + 1) * 3 + g) * HH);
    }
    const F4U* h4 = (const F4U*)hs;
    const int kbase = khalf * 128;           // in float4 units

    for (int s = 0; s < TLEN; s++) {
        int t = dir ? (TLEN - 1 - s) : s;

        // prefetch gate inputs for the tail (overlaps copy + compute)
        float xr = 0.f, xz = 0.f, xn = 0.f;
        if (tail) {
            const float* xgr = g_xg + (size_t)(tb * TLEN + t) * NWALL
                                    + (size_t)dir * K3H;
            xr = __ldg(&xgr[tj]);
            xz = __ldg(&xgr[HH + tj]);
            xn = __ldg(&xgr[2 * HH + tj]);
        }

        // refresh hidden state (L1-bypassed: lines written by other SMs)
        const float4* hprev = (const float4*)&g_hbuf[s & 1][dir][0];
        float4* hs4 = (float4*)hs;
        #pragma unroll
        for (int idx = threadIdx.x; idx < BATCHN * HH / 4; idx += 512)
            hs4[idx] = __ldcg(&hprev[idx]);
        __syncthreads();

        u64 acc[2][3][4];
        #pragma unroll
        for (int jj = 0; jj < 2; jj++)
            #pragma unroll
            for (int g = 0; g < 3; g++)
                #pragma unroll
                for (int b = 0; b < 4; b++) acc[jj][g][b] = 0ull;

        #pragma unroll
        for (int i = 0; i < 8; i++) {
            int kq = kbase + i * 16 + kg;
            F4U w0A = wA[0][kq], w1A = wA[1][kq], w2A = wA[2][kq];
            F4U w0B = wB[0][kq], w1B = wB[1][kq], w2B = wB[2][kq];
            #pragma unroll
            for (int b = 0; b < 4; b++) {
                F4U hv = h4[(bh * 4 + b) * 256 + kq];
                fma2(acc[0][0][b], w0A.u[0], hv.u[0]);
                fma2(acc[0][1][b], w1A.u[0], hv.u[0]);
                fma2(acc[0][2][b], w2A.u[0], hv.u[0]);
                fma2(acc[1][0][b], w0B.u[0], hv.u[0]);
                fma2(acc[1][1][b], w1B.u[0], hv.u[0]);
                fma2(acc[1][2][b], w2B.u[0], hv.u[0]);
                fma2(acc[0][0][b], w0A.u[1], hv.u[1]);
                fma2(acc[0][1][b], w1A.u[1], hv.u[1]);
                fma2(acc[0][2][b], w2A.u[1], hv.u[1]);
                fma2(acc[1][0][b], w0B.u[1], hv.u[1]);
                fma2(acc[1][1][b], w1B.u[1], hv.u[1]);
                fma2(acc[1][2][b], w2B.u[1], hv.u[1]);
            }
        }

        // collapse pairs + reduce over the 16 kg lanes (xor < 16 keeps bh half)
        float red[2][3][4];
        #pragma unroll
        for (int jj = 0; jj < 2; jj++)
            #pragma unroll
            for (int g = 0; g < 3; g++)
                #pragma unroll
                for (int b = 0; b < 4; b++) {
                    float2 p = upk(acc[jj][g][b]);
                    red[jj][g][b] = p.x + p.y;
                }
        #pragma unroll
        for (int off = 8; off > 0; off >>= 1)
            #pragma unroll
            for (int jj = 0; jj < 2; jj++)
                #pragma unroll
                for (int g = 0; g < 3; g++)
                    #pragma unroll
                    for (int b = 0; b < 4; b++)
                        red[jj][g][b] += __shfl_xor_sync(0xffffffffu, red[jj][g][b], off);

        // one lane per half publishes its 24 partials
        if (kg == 0) {
            float* dst = sred + warp * 48 + bh * 4;
            #pragma unroll
            for (int jj = 0; jj < 2; jj++)
                #pragma unroll
                for (int g = 0; g < 3; g++)
                    #pragma unroll
                    for (int b = 0; b < 4; b++)
                        dst[(jj * 3 + g) * 8 + b] = red[jj][g][b];
        }
        __syncthreads();

        if (tail) {
            int base = ((lane >> 3) * 3) * 8 + tb;        // (jj_local*3+g)*8+b
            const float* rA = sred + wp * 48;             // khalf 0
            const float* rB = sred + (wp + 8) * 48;       // khalf 1
            float hr = rA[base]      + rB[base]      + bh_r;
            float hz = rA[base + 8]  + rB[base + 8]  + bh_z;
            float hn = rA[base + 16] + rB[base + 16] + bh_n;
            float r  = 1.f / (1.f + expf(-(xr + hr)));
            float z  = 1.f / (1.f + expf(-(xz + hz)));
            float nn = tanhf(xn + r * hn);
            float hp = hs[tb * HH + tj];
            float hnew = (1.f - z) * nn + z * hp;
            g_hbuf[(s + 1) & 1][dir][tb * HH + tj] = hnew;
            g_flat[(size_t)(tb * TLEN + t) * GOUT + dir * HH + tj] =
                hnew > 0.f ? hnew : 0.01f * hnew;
        }
        grid_sync_dir(dir);
    }
}

// ---------------- gating: warp per token ----------------
__global__ void gate_kernel(const float* __restrict__ gW, const float* __restrict__ gb) {
    int gwid = (blockIdx.x * blockDim.x + threadIdx.x) >> 5;
    int lane = threadIdx.x & 31;
    if (gwid >= NTOK) return;
    const float* f = g_flat + (size_t)gwid * GOUT;
    float acc[NE];
    #pragma unroll
    for (int e = 0; e < NE; e++) acc[e] = 0.f;
    for (int k = lane; k < GOUT; k += 32) {
        float fv = f[k];
        #pragma unroll
        for (int e = 0; e < NE; e++) acc[e] = fmaf(fv, gW[e * GOUT + k], acc[e]);
    }
    #pragma unroll
    for (int e = 0; e < NE; e++)
        #pragma unroll
        for (int off = 16; off > 0; off >>= 1)
            acc[e] += __shfl_xor_sync(0xffffffffu, acc[e], off);

    if (lane == 0) {
        float l[NE], mx = -1e30f;
        #pragma unroll
        for (int e = 0; e < NE; e++) { l[e] = acc[e] + gb[e]; mx = fmaxf(mx, l[e]); }
        float se = 0.f;
        #pragma unroll
        for (int e = 0; e < NE; e++) se += expf(l[e] - mx);
        float lse = mx + logf(se);
        float sc[NE];
        #pragma unroll
        for (int e = 0; e < NE; e++) sc[e] = expf(l[e] - lse);
        int e0 = 0; float s0 = sc[0];
        #pragma unroll
        for (int e = 1; e < NE; e++) if (sc[e] > s0) { s0 = sc[e]; e0 = e; }
        int e1 = -1; float s1 = -1e30f;
        #pragma unroll
        for (int e = 0; e < NE; e++) if (e != e0 && sc[e] > s1) { s1 = sc[e]; e1 = e; }
        float inv = 1.f / (s0 + s1);
        int p0 = atomicAdd(&g_cnt[e0], 1);
        g_list[e0][p0] = gwid * 2;
        int p1 = atomicAdd(&g_cnt[e1], 1);
        g_list[e1][p1] = gwid * 2 + 1;
        g_wt[gwid * 2]     = s0 * inv;
        g_wt[gwid * 2 + 1] = s1 * inv;
        atomicAdd(&g_zsum, lse * lse);
        #pragma unroll
        for (int e = 0; e < NE; e++) atomicAdd(&g_Psum[e], sc[e]);
    }
}

// ---------------- deterministic combine ----------------
__global__ void combine_kernel(float* __restrict__ out) {
    int idx = blockIdx.x * blockDim.x + threadIdx.x;
    if (idx >= NTOK * DM) return;
    int t = idx >> 9;
    int d = idx & (DM - 1);
    out[idx] = g_wt[2 * t]     * g_obuf[(size_t)(2 * t) * DM + d]
             + g_wt[2 * t + 1] * g_obuf[(size_t)(2 * t + 1) * DM + d];
}

// ---------------- aux loss scalar ----------------
__global__ void aux_kernel(float* out, int out_size) {
    if (out_size <= NTOK * DM) return;
    float s = 0.f;
    #pragma unroll
    for (int e = 0; e < NE; e++)
        s += ((float)g_cnt[e] / (float)NTOK) * (g_Psum[e] / (float)NTOK);
    out[NTOK * DM] = 0.01f * (float)NE * s + 0.001f * (g_zsum / (float)NTOK);
}

// ---------------- launch ----------------
extern "C" void kernel_launch(void* const* d_in, const int* in_sizes, int n_in,
                              void* d_out, int out_size) {
    const float* x   = (const float*)d_in[0];
    const float* Wih = (const float*)d_in[1];
    const float* Whh = (const float*)d_in[2];
    const float* bih = (const float*)d_in[3];
    const float* bhh = (const float*)d_in[4];
    const float* gW  = (const float*)d_in[5];
    const float* gb  = (const float*)d_in[6];
    const float* W1  = (const float*)d_in[7];
    const float* b1  = (const float*)d_in[8];
    const float* W2  = (const float*)d_in[9];
    const float* b2  = (const float*)d_in[10];
    float* out = (float*)d_out;

    float *p_xg, *p_flat, *p_h1, *p_obuf, *p_wT;
    cudaGetSymbolAddress((void**)&p_xg,   g_xg);
    cudaGetSymbolAddress((void**)&p_flat, g_flat);
    cudaGetSymbolAddress((void**)&p_h1,   g_h1);
    cudaGetSymbolAddress((void**)&p_obuf, g_obuf);
    cudaGetSymbolAddress((void**)&p_wT,   g_wT);

    cudaFuncSetAttribute(gru_persist,
                         cudaFuncAttributeMaxDynamicSharedMemorySize, GRU_SMEM);

    init_kernel<<<256, 256>>>();
    transpose_w<<<dim3(16, 192), dim3(32, 8)>>>(Wih);

    // xg = x @ Wih^T + bih : M=8192, N=6144, K=512
    gemm128<<<dim3(48, 64, 1), 256>>>(x, DM, p_wT, NWALL, bih, 0,
                                      p_xg, NWALL, NTOK, NWALL, DM,
                                      0, 0, 0, 0L);

    // bidirectional GRU: one persistent kernel, Whh SMEM-resident
    gru_persist<<<GRU_CTAS, 512, GRU_SMEM>>>(Whh, bhh);

    gate_kernel<<<NTOK / 8, 256>>>(gW, gb);

    // expert GEMM1 + GELU (gathered rows of flat)
    gemm128<<<dim3(16, 64, 8), 256>>>(p_flat, GOUT, W1, FFND, b1, FFND,
                                      p_h1, FFND, 0, FFND, GOUT,
                                      1, 1, 1, (long)GOUT * FFND);
    // expert GEMM2
    gemm128<<<dim3(4, 64, 8), 256>>>(p_h1, FFND, W2, DM, b2, DM,
                                     p_obuf, DM, 0, DM, FFND,
                                     1, 0, 0, (long)FFND * DM);

    combine_kernel<<<(NTOK * DM + 255) / 256, 256>>>(out);
    aux_kernel<<<1, 1>>>(out, out_size);
}